// round 16
// baseline (speedup 1.0000x reference)
#include <cuda_runtime.h>
#include <cuda_bf16.h>
#include <cstdint>
#include <math.h>

// ---------------------------------------------------------------------------
// Problem constants: B=4, L=8192, D=768, K=24, NFFT=16384.
// Math: out[t] = 2 * sum_{j even, j<=t} v[j] * u[t-j]
//   => two length-4096 causal convs with v_e[i]=v[2i], fused into ONE complex
//      FFT of size 8192 via z[k] = u[2k] + i*u[2k+1].
// GEMM u = x @ M_inputs: 3-term bf16 split (AH*BH + AH*BL + AL*BH), fused in
// a single k-sweep with 4 operand planes per stage.
// FFTs use a two-level twiddle table (W^e = twhi[e>>6] * twlo[e&63]) --
// conv was MUFU-bound on __sincosf (0.5 op/cyc/SM); tables move the work to
// the FMA pipe.
// ---------------------------------------------------------------------------

#define BATCH 4
#define SEQ   8192
#define DIM   768
#define NK    24
#define NC    8192
#define HALF  4096

#define SMX(i) ((i) + ((i) >> 4))
#define FFT_BUF 8704
#define FFT_SMEM_BYTES (2 * FFT_BUF * (int)sizeof(float2))   // 139264 (filter)
#define CONV_SMEM_BYTES (FFT_BUF * (int)sizeof(float2))      // 69632 (conv, 1 buf)

// Scratch (device globals: no allocation allowed anywhere)
__device__ float    g_XT[(size_t)BATCH * DIM * SEQ];   // (B, D, L) fp32, in place
__device__ float2   g_VS[(size_t)DIM * NC];            // filter spectra
__device__ uint32_t g_AHw[(size_t)BATCH * SEQ * DIM / 2];  // x hi, bf16 pairs
__device__ uint32_t g_ALw[(size_t)BATCH * SEQ * DIM / 2];  // x lo
__device__ uint32_t g_BHw[(size_t)DIM * DIM / 2];          // Mi^T hi, [n][k] pairs
__device__ uint32_t g_BLw[(size_t)DIM * DIM / 2];          // Mi^T lo

// ---------------------------------------------------------------------------
// complex helpers
// ---------------------------------------------------------------------------
__device__ __forceinline__ float2 cmul(float2 a, float2 b) {
    return make_float2(a.x * b.x - a.y * b.y, a.x * b.y + a.y * b.x);
}

template<int DIR>
__device__ __forceinline__ void dft4(float2& a, float2& b, float2& c, float2& d) {
    float2 t0 = make_float2(a.x + c.x, a.y + c.y);
    float2 t1 = make_float2(a.x - c.x, a.y - c.y);
    float2 t2 = make_float2(b.x + d.x, b.y + d.y);
    float2 t3 = make_float2(b.x - d.x, b.y - d.y);
    a = make_float2(t0.x + t2.x, t0.y + t2.y);
    c = make_float2(t0.x - t2.x, t0.y - t2.y);
    if (DIR == -1) {
        b = make_float2(t1.x + t3.y, t1.y - t3.x);
        d = make_float2(t1.x - t3.y, t1.y + t3.x);
    } else {
        b = make_float2(t1.x - t3.y, t1.y + t3.x);
        d = make_float2(t1.x + t3.y, t1.y - t3.x);
    }
}

template<int DIR>
__device__ __forceinline__ void dft8(float2 v[8]) {
    const float S = 0.7071067811865476f;
    float2 e0 = v[0], e1 = v[2], e2 = v[4], e3 = v[6];
    float2 o0 = v[1], o1 = v[3], o2 = v[5], o3 = v[7];
    dft4<DIR>(e0, e1, e2, e3);
    dft4<DIR>(o0, o1, o2, o3);
    o1 = cmul(o1, make_float2(S, (float)DIR * S));
    o2 = (DIR == -1) ? make_float2(o2.y, -o2.x) : make_float2(-o2.y, o2.x);
    o3 = cmul(o3, make_float2(-S, (float)DIR * S));
    v[0] = make_float2(e0.x + o0.x, e0.y + o0.y); v[4] = make_float2(e0.x - o0.x, e0.y - o0.y);
    v[1] = make_float2(e1.x + o1.x, e1.y + o1.y); v[5] = make_float2(e1.x - o1.x, e1.y - o1.y);
    v[2] = make_float2(e2.x + o2.x, e2.y + o2.y); v[6] = make_float2(e2.x - o2.x, e2.y - o2.y);
    v[3] = make_float2(e3.x + o3.x, e3.y + o3.y); v[7] = make_float2(e3.x - o3.x, e3.y - o3.y);
}

// log-depth twiddle powers: p[r] = w1^(r+1) for r=0..6
template<int DIR>
__device__ __forceinline__ void twpow(float2 w1, float2 p[7]) {
    p[0] = w1;
    p[1] = cmul(w1, w1);
    p[2] = cmul(p[1], w1);
    p[3] = cmul(p[1], p[1]);
    p[4] = cmul(p[3], w1);
    p[5] = cmul(p[3], p[1]);
    p[6] = cmul(p[3], p[2]);
}

// twiddle table lookup: W^e for DIR=-1, conj for DIR=+1 (e in [0,4096))
template<int DIR>
__device__ __forceinline__ float2 twget(const float2* lo, const float2* hi, int e) {
    float2 w = cmul(hi[e >> 6], lo[e & 63]);
    if (DIR == 1) w.y = -w.y;
    return w;
}

// build tables: lo[j] = W^j, hi[j] = W^(64j), W = e^{-2*pi*i/8192}
__device__ __forceinline__ void twinit(float2* lo, float2* hi, int tid) {
    if (tid < 64) {
        float c, s;
        sincosf(-6.283185307179586f * (float)tid / 8192.0f, &s, &c);
        lo[tid] = make_float2(c, s);
        sincosf(-6.283185307179586f * (float)tid / 128.0f, &s, &c);
        hi[tid] = make_float2(c, s);
    }
}

// ---- two-buffer helpers (filter kernel, 512 threads) ----
template<int DIR>
__device__ __forceinline__ void fft_stage(const float2* s, float2* d, int Ns, int tid,
                                          const float2* lo, const float2* hi) {
    const int estep = 1024 / Ns;
    #pragma unroll
    for (int it = 0; it < 2; it++) {
        int j  = tid + it * 512;
        int jm = j & (Ns - 1);
        float2 w1 = twget<DIR>(lo, hi, jm * estep);
        float2 p[7];
        twpow<DIR>(w1, p);
        float2 v[8];
        v[0] = s[SMX(j)];
        #pragma unroll
        for (int r = 1; r < 8; r++) v[r] = cmul(s[SMX(j + r * 1024)], p[r - 1]);
        dft8<DIR>(v);
        int base = ((j & ~(Ns - 1)) << 3) + jm;
        #pragma unroll
        for (int r = 0; r < 8; r++) d[SMX(base + r * Ns)] = v[r];
    }
    __syncthreads();
}

template<int DIR>
__device__ __forceinline__ void fft_r2(const float2* s, float2* d, int tid,
                                       const float2* lo, const float2* hi) {
    #pragma unroll
    for (int it = 0; it < 8; it++) {
        int j = tid + it * 512;
        float2 w = twget<DIR>(lo, hi, j);
        float2 v0 = s[SMX(j)];
        float2 v1 = cmul(s[SMX(j + 4096)], w);
        d[SMX(j)]        = make_float2(v0.x + v1.x, v0.y + v1.y);
        d[SMX(j + 4096)] = make_float2(v0.x - v1.x, v0.y - v1.y);
    }
    __syncthreads();
}

template<int DIR>
__device__ __forceinline__ void fft8192(float2* src, float2* dst, int tid,
                                        const float2* lo, const float2* hi) {
    #pragma unroll
    for (int it = 0; it < 2; it++) {
        int j = tid + it * 512;
        float2 v[8];
        #pragma unroll
        for (int r = 0; r < 8; r++) v[r] = src[SMX(j + r * 1024)];
        dft8<DIR>(v);
        #pragma unroll
        for (int r = 0; r < 8; r++) dst[SMX(j * 8 + r)] = v[r];
    }
    __syncthreads();
    fft_stage<DIR>(dst, src, 8, tid, lo, hi);
    fft_stage<DIR>(src, dst, 64, tid, lo, hi);
    fft_stage<DIR>(dst, src, 512, tid, lo, hi);
    fft_r2<DIR>(src, dst, tid, lo, hi);
}

// ---- IN-PLACE helpers (conv kernel, 512 threads, single buffer) ----
template<int DIR>
__device__ __forceinline__ void fft_stage_ip(float2* s, int Ns, int tid,
                                             const float2* lo, const float2* hi) {
    float2 v[2][8];
    #pragma unroll
    for (int it = 0; it < 2; it++) {
        int j = tid + it * 512;
        #pragma unroll
        for (int r = 0; r < 8; r++) v[it][r] = s[SMX(j + r * 1024)];
    }
    __syncthreads();
    const int estep = 1024 / Ns;
    #pragma unroll
    for (int it = 0; it < 2; it++) {
        int j  = tid + it * 512;
        int jm = j & (Ns - 1);
        float2 w1 = twget<DIR>(lo, hi, jm * estep);
        float2 p[7];
        twpow<DIR>(w1, p);
        #pragma unroll
        for (int r = 1; r < 8; r++) v[it][r] = cmul(v[it][r], p[r - 1]);
        dft8<DIR>(v[it]);
        int base = ((j & ~(Ns - 1)) << 3) + jm;
        #pragma unroll
        for (int r = 0; r < 8; r++) s[SMX(base + r * Ns)] = v[it][r];
    }
    __syncthreads();
}

template<int DIR>
__device__ __forceinline__ void fft_r2_ip(float2* s, int tid,
                                          const float2* lo, const float2* hi) {
    #pragma unroll
    for (int it = 0; it < 8; it++) {
        int j = tid + it * 512;
        float2 w = twget<DIR>(lo, hi, j);
        float2 v0 = s[SMX(j)];
        float2 v1 = cmul(s[SMX(j + 4096)], w);
        s[SMX(j)]        = make_float2(v0.x + v1.x, v0.y + v1.y);
        s[SMX(j + 4096)] = make_float2(v0.x - v1.x, v0.y - v1.y);
    }
    __syncthreads();
}

// ---------------------------------------------------------------------------
// bf16 split helpers
// ---------------------------------------------------------------------------
__device__ __forceinline__ uint32_t pkbf(float lo, float hi) {
    uint32_t r;
    asm("cvt.rn.bf16x2.f32 %0, %1, %2;" : "=r"(r) : "f"(hi), "f"(lo));
    return r;
}
__device__ __forceinline__ float bfhi(float x) {
    return __bfloat162float(__float2bfloat16_rn(x));
}

// ---------------------------------------------------------------------------
// Pre-pass P1: split x -> AH/AL bf16 planes
// ---------------------------------------------------------------------------
__global__ void __launch_bounds__(256)
split_x_kernel(const float* __restrict__ X) {
    int i = blockIdx.x * 256 + threadIdx.x;
    float4 v = *(const float4*)(X + (size_t)i * 4);
    float h0 = bfhi(v.x), h1 = bfhi(v.y), h2 = bfhi(v.z), h3 = bfhi(v.w);
    g_AHw[(size_t)i * 2]     = pkbf(h0, h1);
    g_AHw[(size_t)i * 2 + 1] = pkbf(h2, h3);
    g_ALw[(size_t)i * 2]     = pkbf(v.x - h0, v.y - h1);
    g_ALw[(size_t)i * 2 + 1] = pkbf(v.z - h2, v.w - h3);
}

// ---------------------------------------------------------------------------
// Pre-pass P2: split + transpose Mi [k][n] -> BH/BL [n][k] bf16 pairs
// ---------------------------------------------------------------------------
__global__ void __launch_bounds__(256)
split_b_kernel(const float* __restrict__ Mi) {
    int idx = blockIdx.x * 256 + threadIdx.x;
    int n  = idx % DIM;
    int kp = idx / DIM;
    float v0 = Mi[(size_t)(2 * kp) * DIM + n];
    float v1 = Mi[(size_t)(2 * kp + 1) * DIM + n];
    float h0 = bfhi(v0), h1 = bfhi(v1);
    g_BHw[(size_t)n * (DIM / 2) + kp] = pkbf(h0, h1);
    g_BLw[(size_t)n * (DIM / 2) + kp] = pkbf(v0 - h0, v1 - h1);
}

// ---------------------------------------------------------------------------
// Kernel 1: filter prep. One CTA per output channel d.
// ---------------------------------------------------------------------------
__global__ void __launch_bounds__(512, 1)
filter_kernel(const float* __restrict__ phi, const float* __restrict__ Mf) {
    extern __shared__ float2 fb[];
    float2* A  = fb;
    float2* Bu = fb + FFT_BUF;
    __shared__ float mf[NK];
    __shared__ float2 twlo[64], twhi[64];

    const int tid = threadIdx.x;
    const int d   = blockIdx.x;
    if (tid < NK) mf[tid] = Mf[tid * DIM + d];
    twinit(twlo, twhi, tid);
    __syncthreads();

    const float sc = 2.0f / 8192.0f;
    #pragma unroll 1
    for (int it = 0; it < 16; it++) {
        int i = tid + it * 512;
        float s = 0.0f;
        if (i < HALF) {
            const float* pr = phi + (size_t)i * (2 * NK);
            #pragma unroll
            for (int k = 0; k < NK; k++) s += pr[k] * mf[k];
        }
        A[SMX(i)] = make_float2(s * sc, 0.0f);
    }
    __syncthreads();

    fft8192<-1>(A, Bu, tid, twlo, twhi);

    float2* vsd = g_VS + ((size_t)d << 13);
    #pragma unroll 1
    for (int it = 0; it < 16; it++) {
        int i = tid + it * 512;
        vsd[i] = Bu[SMX(i)];
    }
}

// ---------------------------------------------------------------------------
// GEMM: fused 3-term bf16 kernel. CTA 128M x 128N, warp tile 64x32,
// 24 K-chunks of 32; each stage holds 4 planes (AH, AL, BH, BL) of 8KB,
// APITCH=80 (conflict-free ldmatrix). 2-stage cp.async ring, 2 CTAs/SM.
// ---------------------------------------------------------------------------
__device__ __forceinline__ uint32_t smem_u32(const void* p) {
    uint32_t a;
    asm("{ .reg .u64 t; cvta.to.shared.u64 t, %1; cvt.u32.u64 %0, t; }" : "=r"(a) : "l"(p));
    return a;
}
__device__ __forceinline__ void cpa16(uint32_t dst, const void* src) {
    asm volatile("cp.async.cg.shared.global [%0], [%1], 16;" :: "r"(dst), "l"(src));
}
__device__ __forceinline__ void ldsm4(uint32_t* r, uint32_t addr) {
    asm volatile("ldmatrix.sync.aligned.m8n8.x4.shared.b16 {%0,%1,%2,%3}, [%4];"
                 : "=r"(r[0]), "=r"(r[1]), "=r"(r[2]), "=r"(r[3]) : "r"(addr));
}
__device__ __forceinline__ void mma16(float4& d,
                                      uint32_t a0, uint32_t a1, uint32_t a2, uint32_t a3,
                                      uint32_t b0, uint32_t b1) {
    asm volatile(
        "mma.sync.aligned.m16n8k16.row.col.f32.bf16.bf16.f32 "
        "{%0,%1,%2,%3}, {%4,%5,%6,%7}, {%8,%9}, {%0,%1,%2,%3};"
        : "+f"(d.x), "+f"(d.y), "+f"(d.z), "+f"(d.w)
        : "r"(a0), "r"(a1), "r"(a2), "r"(a3), "r"(b0), "r"(b1));
}

#define APITCH 80                    // bytes per 32-k row (64B data + 16B pad)
#define PLANE  (128 * APITCH)        // 10240 per plane
#define STG_BYTES (4 * PLANE)        // 40960: AH, AL, BH, BL
#define GEMM_DYN_BYTES (2 * STG_BYTES)   // 81920, 2 stages
#define NCHUNK 24

__device__ __forceinline__ void gemm_issue(int kc, uint32_t sbase, int tid,
                                           int l0, int n0) {
    uint32_t st = sbase + (uint32_t)(kc & 1) * STG_BYTES;
    int row  = tid >> 1;
    int half = tid & 1;
    size_t aoffg = (size_t)(l0 + row) * (DIM / 2) + kc * 16 + half * 8;
    size_t boffg = (size_t)(n0 + row) * (DIM / 2) + kc * 16 + half * 8;
    uint32_t dst = st + (uint32_t)(row * APITCH + half * 32);
    cpa16(dst,                  g_AHw + aoffg);
    cpa16(dst + 16,             g_AHw + aoffg + 4);
    cpa16(dst + PLANE,          g_ALw + aoffg);
    cpa16(dst + PLANE + 16,     g_ALw + aoffg + 4);
    cpa16(dst + 2 * PLANE,      g_BHw + boffg);
    cpa16(dst + 2 * PLANE + 16, g_BHw + boffg + 4);
    cpa16(dst + 3 * PLANE,      g_BLw + boffg);
    cpa16(dst + 3 * PLANE + 16, g_BLw + boffg + 4);
    asm volatile("cp.async.commit_group;" ::: "memory");
}

__global__ void __launch_bounds__(256, 2)
gemm_kernel(int dummy) {
    extern __shared__ uint8_t smem_raw[];
    const uint32_t sbase = smem_u32(smem_raw);

    const int tid  = threadIdx.x;
    const int wid  = tid >> 5;
    const int lane = tid & 31;
    const int g    = lane >> 2;
    const int tig  = lane & 3;
    const int m0   = (wid & 1) * 64;
    const int nw0  = (wid >> 1) * 32;

    const int n0 = blockIdx.x * 128;
    const int l0 = blockIdx.y * 128;

    gemm_issue(0, sbase, tid, l0, n0);

    float4 acc[4][4];
    #pragma unroll
    for (int mt = 0; mt < 4; mt++)
        #pragma unroll
        for (int nt = 0; nt < 4; nt++)
            acc[mt][nt] = make_float4(0.f, 0.f, 0.f, 0.f);

    const uint32_t aoff = (uint32_t)((m0 + (lane & 15)) * APITCH + (lane >> 4) * 16);
    const uint32_t boff = (uint32_t)((nw0 + (lane & 7) + ((lane >> 4) << 3)) * APITCH
                        + ((lane >> 3) & 1) * 16);

    #pragma unroll 1
    for (int c = 0; c < NCHUNK; c++) {
        asm volatile("cp.async.wait_group 0;" ::: "memory");
        __syncthreads();
        if (c < NCHUNK - 1) gemm_issue(c + 1, sbase, tid, l0, n0);

        const uint32_t st = sbase + (uint32_t)(c & 1) * STG_BYTES;
        #pragma unroll
        for (int ks = 0; ks < 2; ks++) {
            const uint32_t ko = (uint32_t)(ks * 32);
            uint32_t aH[4][4];
            #pragma unroll
            for (int mt = 0; mt < 4; mt++)
                ldsm4(aH[mt], st + aoff + (uint32_t)(mt * 16 * APITCH) + ko);
            uint32_t bH[2][4];
            #pragma unroll
            for (int nh = 0; nh < 2; nh++)
                ldsm4(bH[nh], st + 2 * PLANE + boff + (uint32_t)(nh * 16 * APITCH) + ko);
            #pragma unroll
            for (int mt = 0; mt < 4; mt++)
                #pragma unroll
                for (int nt = 0; nt < 4; nt++)
                    mma16(acc[mt][nt], aH[mt][0], aH[mt][1], aH[mt][2], aH[mt][3],
                          bH[nt >> 1][(nt & 1) * 2], bH[nt >> 1][(nt & 1) * 2 + 1]);
            {
                uint32_t bL[2][4];
                #pragma unroll
                for (int nh = 0; nh < 2; nh++)
                    ldsm4(bL[nh], st + 3 * PLANE + boff + (uint32_t)(nh * 16 * APITCH) + ko);
                #pragma unroll
                for (int mt = 0; mt < 4; mt++)
                    #pragma unroll
                    for (int nt = 0; nt < 4; nt++)
                        mma16(acc[mt][nt], aH[mt][0], aH[mt][1], aH[mt][2], aH[mt][3],
                              bL[nt >> 1][(nt & 1) * 2], bL[nt >> 1][(nt & 1) * 2 + 1]);
            }
            {
                uint32_t aL[4][4];
                #pragma unroll
                for (int mt = 0; mt < 4; mt++)
                    ldsm4(aL[mt], st + PLANE + aoff + (uint32_t)(mt * 16 * APITCH) + ko);
                #pragma unroll
                for (int mt = 0; mt < 4; mt++)
                    #pragma unroll
                    for (int nt = 0; nt < 4; nt++)
                        mma16(acc[mt][nt], aL[mt][0], aL[mt][1], aL[mt][2], aL[mt][3],
                              bH[nt >> 1][(nt & 1) * 2], bH[nt >> 1][(nt & 1) * 2 + 1]);
            }
        }
    }

    const int b    = l0 >> 13;
    const int lloc = l0 & (SEQ - 1);
    #pragma unroll
    for (int mt = 0; mt < 4; mt++) {
        const int lbase = lloc + m0 + mt * 16 + g;
        #pragma unroll
        for (int nt = 0; nt < 4; nt++) {
            const int d0 = n0 + nw0 + nt * 8 + 2 * tig;
            float4 cc = acc[mt][nt];
            float* pa = g_XT + (((size_t)(b * DIM + d0)) << 13) + lbase;
            float* pb = g_XT + (((size_t)(b * DIM + d0 + 1)) << 13) + lbase;
            pa[0] = cc.x; pb[0] = cc.y;
            pa[8] = cc.z; pb[8] = cc.w;
        }
    }
}

// ---------------------------------------------------------------------------
// Kernel 3: per-(b,d) FFT convolution, in place on g_XT rows. 512 threads,
// single smem buffer (in-place register-staged stages), 2 CTAs/SM,
// table-based twiddles (no MUFU in the hot path).
// ---------------------------------------------------------------------------
__global__ void __launch_bounds__(512, 2)
conv_kernel() {
    extern __shared__ float2 A[];
    __shared__ float2 twlo[64], twhi[64];

    const int tid = threadIdx.x;
    const int d   = blockIdx.x >> 2;
    const int b   = blockIdx.x & 3;

    float2* row = (float2*)(g_XT + (((size_t)(b * DIM + d)) << 13));
    const float2* vs = g_VS + ((size_t)d << 13);

    twinit(twlo, twhi, tid);

    // ---- forward FFT: stage 1 (Ns=1, no twiddle) straight from global ----
    #pragma unroll
    for (int it = 0; it < 2; it++) {
        int j = tid + it * 512;
        float2 v[8];
        #pragma unroll
        for (int r = 0; r < 8; r++)
            v[r] = (r < 4) ? row[j + r * 1024] : make_float2(0.0f, 0.0f);
        dft8<-1>(v);
        #pragma unroll
        for (int r = 0; r < 8; r++) A[SMX(j * 8 + r)] = v[r];
    }
    __syncthreads();
    fft_stage_ip<-1>(A, 8, tid, twlo, twhi);
    fft_stage_ip<-1>(A, 64, tid, twlo, twhi);
    fft_stage_ip<-1>(A, 512, tid, twlo, twhi);
    fft_r2_ip<-1>(A, tid, twlo, twhi);     // spectrum now in A

    // ---- inverse FFT: stage 1 (Ns=1) with fused spectral multiply ----
    {
        float2 v[2][8];
        #pragma unroll
        for (int it = 0; it < 2; it++) {
            int j = tid + it * 512;
            #pragma unroll
            for (int r = 0; r < 8; r++) {
                int idx = j + r * 1024;
                v[it][r] = cmul(A[SMX(idx)], vs[idx]);
            }
        }
        __syncthreads();
        #pragma unroll
        for (int it = 0; it < 2; it++) {
            int j = tid + it * 512;
            dft8<1>(v[it]);
            #pragma unroll
            for (int r = 0; r < 8; r++) A[SMX(j * 8 + r)] = v[it][r];
        }
        __syncthreads();
    }
    fft_stage_ip<1>(A, 8, tid, twlo, twhi);
    fft_stage_ip<1>(A, 64, tid, twlo, twhi);
    fft_stage_ip<1>(A, 512, tid, twlo, twhi);

    // ---- inverse final radix-2: write the needed half straight to global ----
    #pragma unroll
    for (int it = 0; it < 8; it++) {
        int j = tid + it * 512;            // 0..4095
        float2 w = twget<1>(twlo, twhi, j);
        float2 v0 = A[SMX(j)];
        float2 v1 = cmul(A[SMX(j + 4096)], w);
        row[j] = make_float2(v0.x + v1.x, v0.y + v1.y);
    }
}

// ---------------------------------------------------------------------------
// Kernel 4: transpose g_XT (B,D,L) -> out (B,L,D)
// ---------------------------------------------------------------------------
__global__ void __launch_bounds__(256, 4)
transpose_kernel(float* __restrict__ out) {
    __shared__ float t[32][33];
    const int b  = blockIdx.z;
    const int l0 = blockIdx.x * 32;
    const int d0 = blockIdx.y * 32;
    const int tx = threadIdx.x, ty = threadIdx.y;   // 32 x 8

    const float* src = g_XT + (size_t)b * DIM * SEQ;
    #pragma unroll
    for (int i = 0; i < 4; i++)
        t[ty + i * 8][tx] = src[(size_t)(d0 + ty + i * 8) * SEQ + l0 + tx];
    __syncthreads();
    float* dst = out + (size_t)b * SEQ * DIM;
    #pragma unroll
    for (int i = 0; i < 4; i++)
        dst[(size_t)(l0 + ty + i * 8) * DIM + d0 + tx] = t[tx][ty + i * 8];
}

// ---------------------------------------------------------------------------
// launch
// ---------------------------------------------------------------------------
extern "C" void kernel_launch(void* const* d_in, const int* in_sizes, int n_in,
                              void* d_out, int out_size) {
    const float* x   = (const float*)d_in[0];
    const float* phi = (const float*)d_in[1];
    const float* Mi  = (const float*)d_in[2];
    const float* Mf  = (const float*)d_in[3];
    float* out = (float*)d_out;

    cudaFuncSetAttribute(filter_kernel, cudaFuncAttributeMaxDynamicSharedMemorySize, FFT_SMEM_BYTES);
    cudaFuncSetAttribute(conv_kernel,   cudaFuncAttributeMaxDynamicSharedMemorySize, CONV_SMEM_BYTES);
    cudaFuncSetAttribute(gemm_kernel,   cudaFuncAttributeMaxDynamicSharedMemorySize, GEMM_DYN_BYTES);

    split_x_kernel<<<(BATCH * SEQ * DIM / 4) / 256, 256>>>(x);
    split_b_kernel<<<(DIM * DIM / 2) / 256, 256>>>(Mi);
    filter_kernel<<<DIM, 512, FFT_SMEM_BYTES>>>(phi, Mf);
    gemm_kernel<<<dim3(DIM / 128, (BATCH * SEQ) / 128), 256, GEMM_DYN_BYTES>>>(0);
    conv_kernel<<<BATCH * DIM, 512, CONV_SMEM_BYTES>>>();
    transpose_kernel<<<dim3(SEQ / 32, DIM / 32, BATCH), dim3(32, 8)>>>(out);
}

// round 17
// speedup vs baseline: 1.3485x; 1.3485x over previous
#include <cuda_runtime.h>
#include <cuda_bf16.h>
#include <cstdint>

// ---------------------------------------------------------------------------
// Problem constants: B=4, L=8192, D=768, K=24, NFFT=16384.
// Math: out[t] = 2 * sum_{j even, j<=t} v[j] * u[t-j]
//   => two length-4096 causal convs with v_e[i]=v[2i], fused into ONE complex
//      FFT of size 8192 via z[k] = u[2k] + i*u[2k+1].
// Filter spectra by FFT linearity: VS[d] = sum_k Mf[k,d] * FFT(phi_e[:,k])
//   => only NK=24 FFTs + a tiny mixing GEMM (vs 768 FFTs before).
// GEMM u = x @ M_inputs: 3-term bf16 split (AH*BH + AH*BL + AL*BH), fused in
// a single k-sweep with 4 operand planes per stage.
// ---------------------------------------------------------------------------

#define BATCH 4
#define SEQ   8192
#define DIM   768
#define NK    24
#define NC    8192
#define HALF  4096

#define SMX(i) ((i) + ((i) >> 4))
#define FFT_BUF 8704
#define FFT_SMEM_BYTES (2 * FFT_BUF * (int)sizeof(float2))   // 139264

// Scratch (device globals: no allocation allowed anywhere)
__device__ float    g_XT[(size_t)BATCH * DIM * SEQ];   // (B, D, L) fp32, in place
__device__ float2   g_VS[(size_t)DIM * NC];            // filter spectra
__device__ float2   g_PHI[(size_t)NK * NC];            // per-k basis spectra
__device__ uint32_t g_AHw[(size_t)BATCH * SEQ * DIM / 2];  // x hi, bf16 pairs
__device__ uint32_t g_ALw[(size_t)BATCH * SEQ * DIM / 2];  // x lo
__device__ uint32_t g_BHw[(size_t)DIM * DIM / 2];          // Mi^T hi, [n][k] pairs
__device__ uint32_t g_BLw[(size_t)DIM * DIM / 2];          // Mi^T lo

// ---------------------------------------------------------------------------
// complex helpers
// ---------------------------------------------------------------------------
__device__ __forceinline__ float2 cmul(float2 a, float2 b) {
    return make_float2(a.x * b.x - a.y * b.y, a.x * b.y + a.y * b.x);
}

template<int DIR>
__device__ __forceinline__ void dft4(float2& a, float2& b, float2& c, float2& d) {
    float2 t0 = make_float2(a.x + c.x, a.y + c.y);
    float2 t1 = make_float2(a.x - c.x, a.y - c.y);
    float2 t2 = make_float2(b.x + d.x, b.y + d.y);
    float2 t3 = make_float2(b.x - d.x, b.y - d.y);
    a = make_float2(t0.x + t2.x, t0.y + t2.y);
    c = make_float2(t0.x - t2.x, t0.y - t2.y);
    if (DIR == -1) {
        b = make_float2(t1.x + t3.y, t1.y - t3.x);
        d = make_float2(t1.x - t3.y, t1.y + t3.x);
    } else {
        b = make_float2(t1.x - t3.y, t1.y + t3.x);
        d = make_float2(t1.x + t3.y, t1.y - t3.x);
    }
}

template<int DIR>
__device__ __forceinline__ void dft8(float2 v[8]) {
    const float S = 0.7071067811865476f;
    float2 e0 = v[0], e1 = v[2], e2 = v[4], e3 = v[6];
    float2 o0 = v[1], o1 = v[3], o2 = v[5], o3 = v[7];
    dft4<DIR>(e0, e1, e2, e3);
    dft4<DIR>(o0, o1, o2, o3);
    o1 = cmul(o1, make_float2(S, (float)DIR * S));
    o2 = (DIR == -1) ? make_float2(o2.y, -o2.x) : make_float2(-o2.y, o2.x);
    o3 = cmul(o3, make_float2(-S, (float)DIR * S));
    v[0] = make_float2(e0.x + o0.x, e0.y + o0.y); v[4] = make_float2(e0.x - o0.x, e0.y - o0.y);
    v[1] = make_float2(e1.x + o1.x, e1.y + o1.y); v[5] = make_float2(e1.x - o1.x, e1.y - o1.y);
    v[2] = make_float2(e2.x + o2.x, e2.y + o2.y); v[6] = make_float2(e2.x - o2.x, e2.y - o2.y);
    v[3] = make_float2(e3.x + o3.x, e3.y + o3.y); v[7] = make_float2(e3.x - o3.x, e3.y - o3.y);
}

// log-depth twiddle powers: p[r] = w1^(r+1) for r=0..6
template<int DIR>
__device__ __forceinline__ void twpow(float2 w1, float2 p[7]) {
    p[0] = w1;
    p[1] = cmul(w1, w1);
    p[2] = cmul(p[1], w1);
    p[3] = cmul(p[1], p[1]);
    p[4] = cmul(p[3], w1);
    p[5] = cmul(p[3], p[1]);
    p[6] = cmul(p[3], p[2]);
}

// generic radix-8 smem stage (Ns >= 8), ends with syncthreads
template<int DIR>
__device__ __forceinline__ void fft_stage(const float2* s, float2* d, int Ns, int tid) {
    const float angc = (float)DIR * 6.283185307179586f / (8.0f * (float)Ns);
    #pragma unroll
    for (int it = 0; it < 2; it++) {
        int j  = tid + it * 512;
        int jm = j & (Ns - 1);
        float c, sn;
        __sincosf(angc * (float)jm, &sn, &c);
        float2 p[7];
        twpow<DIR>(make_float2(c, sn), p);
        float2 v[8];
        v[0] = s[SMX(j)];
        #pragma unroll
        for (int r = 1; r < 8; r++) v[r] = cmul(s[SMX(j + r * 1024)], p[r - 1]);
        dft8<DIR>(v);
        int base = ((j & ~(Ns - 1)) << 3) + jm;
        #pragma unroll
        for (int r = 0; r < 8; r++) d[SMX(base + r * Ns)] = v[r];
    }
    __syncthreads();
}

// radix-2 final stage (Ns = 4096), smem->smem, ends with sync
template<int DIR>
__device__ __forceinline__ void fft_r2(const float2* s, float2* d, int tid) {
    const float angc2 = (float)DIR * 6.283185307179586f / 8192.0f;
    #pragma unroll
    for (int it = 0; it < 8; it++) {
        int j = tid + it * 512;
        float c, sn;
        __sincosf(angc2 * (float)j, &sn, &c);
        float2 v0 = s[SMX(j)];
        float2 v1 = cmul(s[SMX(j + 4096)], make_float2(c, sn));
        d[SMX(j)]        = make_float2(v0.x + v1.x, v0.y + v1.y);
        d[SMX(j + 4096)] = make_float2(v0.x - v1.x, v0.y - v1.y);
    }
    __syncthreads();
}

// full FFT: src -> dst in smem (512 threads)
template<int DIR>
__device__ __forceinline__ void fft8192(float2* src, float2* dst, int tid) {
    #pragma unroll
    for (int it = 0; it < 2; it++) {
        int j = tid + it * 512;
        float2 v[8];
        #pragma unroll
        for (int r = 0; r < 8; r++) v[r] = src[SMX(j + r * 1024)];
        dft8<DIR>(v);
        #pragma unroll
        for (int r = 0; r < 8; r++) dst[SMX(j * 8 + r)] = v[r];
    }
    __syncthreads();
    fft_stage<DIR>(dst, src, 8, tid);
    fft_stage<DIR>(src, dst, 64, tid);
    fft_stage<DIR>(dst, src, 512, tid);
    fft_r2<DIR>(src, dst, tid);
}

// ---------------------------------------------------------------------------
// bf16 split helpers
// ---------------------------------------------------------------------------
__device__ __forceinline__ uint32_t pkbf(float lo, float hi) {
    uint32_t r;
    asm("cvt.rn.bf16x2.f32 %0, %1, %2;" : "=r"(r) : "f"(hi), "f"(lo));
    return r;
}
__device__ __forceinline__ float bfhi(float x) {
    return __bfloat162float(__float2bfloat16_rn(x));
}

// ---------------------------------------------------------------------------
// Kernel 1: prep — three roles by blockIdx:
//   [0,24):        F1: PHI[k] = FFT(phi_e[:,k] * 2/8192)     (needs FFT smem)
//   [24,1560):     split x -> AH/AL  (8 float4 per thread)
//   [1560,1704):   split+transpose Mi -> BH/BL (4 items per thread)
// F1 blocks first so their long FFTs overlap the split stream.
// ---------------------------------------------------------------------------
#define PREP_F1    24
#define PREP_SX    1536
#define PREP_SB    144
#define PREP_GRID  (PREP_F1 + PREP_SX + PREP_SB)

__global__ void __launch_bounds__(512, 1)
prep_kernel(const float* __restrict__ X, const float* __restrict__ phi,
            const float* __restrict__ Mi) {
    const int blk = blockIdx.x;
    const int tid = threadIdx.x;

    if (blk < PREP_F1) {
        // F1: FFT of phi column k (even rows), scaled
        const int k = blk;
        extern __shared__ float2 fb[];
        float2* A  = fb;
        float2* Bu = fb + FFT_BUF;
        const float sc = 2.0f / 8192.0f;
        #pragma unroll 1
        for (int it = 0; it < 16; it++) {
            int i = tid + it * 512;
            float s = (i < HALF) ? phi[(size_t)(2 * i) * NK + k] * sc : 0.0f;
            A[SMX(i)] = make_float2(s, 0.0f);
        }
        __syncthreads();
        fft8192<-1>(A, Bu, tid);
        float2* dst = g_PHI + (size_t)k * NC;
        #pragma unroll 1
        for (int it = 0; it < 16; it++) {
            int i = tid + it * 512;
            dst[i] = Bu[SMX(i)];
        }
    } else if (blk < PREP_F1 + PREP_SX) {
        // split x
        size_t base = (size_t)(blk - PREP_F1) * 4096;
        #pragma unroll
        for (int q = 0; q < 8; q++) {
            size_t i = base + q * 512 + tid;          // float4 index
            float4 v = *(const float4*)(X + i * 4);
            float h0 = bfhi(v.x), h1 = bfhi(v.y), h2 = bfhi(v.z), h3 = bfhi(v.w);
            g_AHw[i * 2]     = pkbf(h0, h1);
            g_AHw[i * 2 + 1] = pkbf(h2, h3);
            g_ALw[i * 2]     = pkbf(v.x - h0, v.y - h1);
            g_ALw[i * 2 + 1] = pkbf(v.z - h2, v.w - h3);
        }
    } else {
        // split + transpose Mi
        size_t base = (size_t)(blk - PREP_F1 - PREP_SX) * 2048;
        #pragma unroll
        for (int q = 0; q < 4; q++) {
            size_t idx = base + q * 512 + tid;        // < 768*384
            int n  = (int)(idx % DIM);
            int kp = (int)(idx / DIM);
            float v0 = Mi[(size_t)(2 * kp) * DIM + n];
            float v1 = Mi[(size_t)(2 * kp + 1) * DIM + n];
            float h0 = bfhi(v0), h1 = bfhi(v1);
            g_BHw[(size_t)n * (DIM / 2) + kp] = pkbf(h0, h1);
            g_BLw[(size_t)n * (DIM / 2) + kp] = pkbf(v0 - h0, v1 - h1);
        }
    }
}

// ---------------------------------------------------------------------------
// Kernel 2: vs — mix basis spectra: VS[d][f] = sum_k Mf[k][d] * PHI[k][f].
// Tile: 64 d x 128 f per CTA, 256 threads, grid 64x12 = 768.
// ---------------------------------------------------------------------------
__global__ void __launch_bounds__(256)
vs_kernel(const float* __restrict__ Mf) {
    __shared__ float2 sph[NK][128];
    __shared__ float  smf[NK][64];

    const int tid = threadIdx.x;
    const int f0  = (blockIdx.x & 63) * 128;
    const int d0  = (blockIdx.x >> 6) * 64;

    #pragma unroll
    for (int q = 0; q < 12; q++) {
        int e = tid + q * 256;                 // < 24*128
        sph[e >> 7][e & 127] = g_PHI[(size_t)(e >> 7) * NC + f0 + (e & 127)];
    }
    #pragma unroll
    for (int q = 0; q < 6; q++) {
        int e = tid + q * 256;                 // < 24*64
        smf[e >> 6][e & 63] = Mf[(size_t)(e >> 6) * DIM + d0 + (e & 63)];
    }
    __syncthreads();

    #pragma unroll 1
    for (int q = 0; q < 32; q++) {
        int o  = tid + q * 256;                // < 64*128
        int dd = o >> 7;
        int f  = o & 127;
        float2 acc = make_float2(0.0f, 0.0f);
        #pragma unroll
        for (int k = 0; k < NK; k++) {
            float m = smf[k][dd];
            acc.x += m * sph[k][f].x;
            acc.y += m * sph[k][f].y;
        }
        g_VS[((size_t)(d0 + dd) << 13) + f0 + f] = acc;
    }
}

// ---------------------------------------------------------------------------
// GEMM: fused 3-term bf16 kernel. CTA 128M x 128N, warp tile 64x32,
// 24 K-chunks of 32; each stage holds 4 planes (AH, AL, BH, BL) of 8KB,
// APITCH=80 (conflict-free ldmatrix). 2-stage cp.async ring, 2 CTAs/SM.
// ---------------------------------------------------------------------------
__device__ __forceinline__ uint32_t smem_u32(const void* p) {
    uint32_t a;
    asm("{ .reg .u64 t; cvta.to.shared.u64 t, %1; cvt.u32.u64 %0, t; }" : "=r"(a) : "l"(p));
    return a;
}
__device__ __forceinline__ void cpa16(uint32_t dst, const void* src) {
    asm volatile("cp.async.cg.shared.global [%0], [%1], 16;" :: "r"(dst), "l"(src));
}
__device__ __forceinline__ void ldsm4(uint32_t* r, uint32_t addr) {
    asm volatile("ldmatrix.sync.aligned.m8n8.x4.shared.b16 {%0,%1,%2,%3}, [%4];"
                 : "=r"(r[0]), "=r"(r[1]), "=r"(r[2]), "=r"(r[3]) : "r"(addr));
}
__device__ __forceinline__ void mma16(float4& d,
                                      uint32_t a0, uint32_t a1, uint32_t a2, uint32_t a3,
                                      uint32_t b0, uint32_t b1) {
    asm volatile(
        "mma.sync.aligned.m16n8k16.row.col.f32.bf16.bf16.f32 "
        "{%0,%1,%2,%3}, {%4,%5,%6,%7}, {%8,%9}, {%0,%1,%2,%3};"
        : "+f"(d.x), "+f"(d.y), "+f"(d.z), "+f"(d.w)
        : "r"(a0), "r"(a1), "r"(a2), "r"(a3), "r"(b0), "r"(b1));
}

#define APITCH 80                    // bytes per 32-k row (64B data + 16B pad)
#define PLANE  (128 * APITCH)        // 10240 per plane
#define STG_BYTES (4 * PLANE)        // 40960: AH, AL, BH, BL
#define GEMM_DYN_BYTES (2 * STG_BYTES)   // 81920, 2 stages
#define NCHUNK 24

__device__ __forceinline__ void gemm_issue(int kc, uint32_t sbase, int tid,
                                           int l0, int n0) {
    uint32_t st = sbase + (uint32_t)(kc & 1) * STG_BYTES;
    int row  = tid >> 1;
    int half = tid & 1;
    size_t aoffg = (size_t)(l0 + row) * (DIM / 2) + kc * 16 + half * 8;
    size_t boffg = (size_t)(n0 + row) * (DIM / 2) + kc * 16 + half * 8;
    uint32_t dst = st + (uint32_t)(row * APITCH + half * 32);
    cpa16(dst,                  g_AHw + aoffg);
    cpa16(dst + 16,             g_AHw + aoffg + 4);
    cpa16(dst + PLANE,          g_ALw + aoffg);
    cpa16(dst + PLANE + 16,     g_ALw + aoffg + 4);
    cpa16(dst + 2 * PLANE,      g_BHw + boffg);
    cpa16(dst + 2 * PLANE + 16, g_BHw + boffg + 4);
    cpa16(dst + 3 * PLANE,      g_BLw + boffg);
    cpa16(dst + 3 * PLANE + 16, g_BLw + boffg + 4);
    asm volatile("cp.async.commit_group;" ::: "memory");
}

__global__ void __launch_bounds__(256, 2)
gemm_kernel(int dummy) {
    extern __shared__ uint8_t smem_raw[];
    const uint32_t sbase = smem_u32(smem_raw);

    const int tid  = threadIdx.x;
    const int wid  = tid >> 5;
    const int lane = tid & 31;
    const int g    = lane >> 2;
    const int tig  = lane & 3;
    const int m0   = (wid & 1) * 64;
    const int nw0  = (wid >> 1) * 32;

    const int n0 = blockIdx.x * 128;
    const int l0 = blockIdx.y * 128;

    gemm_issue(0, sbase, tid, l0, n0);

    float4 acc[4][4];
    #pragma unroll
    for (int mt = 0; mt < 4; mt++)
        #pragma unroll
        for (int nt = 0; nt < 4; nt++)
            acc[mt][nt] = make_float4(0.f, 0.f, 0.f, 0.f);

    const uint32_t aoff = (uint32_t)((m0 + (lane & 15)) * APITCH + (lane >> 4) * 16);
    const uint32_t boff = (uint32_t)((nw0 + (lane & 7) + ((lane >> 4) << 3)) * APITCH
                        + ((lane >> 3) & 1) * 16);

    #pragma unroll 1
    for (int c = 0; c < NCHUNK; c++) {
        asm volatile("cp.async.wait_group 0;" ::: "memory");
        __syncthreads();
        if (c < NCHUNK - 1) gemm_issue(c + 1, sbase, tid, l0, n0);

        const uint32_t st = sbase + (uint32_t)(c & 1) * STG_BYTES;
        #pragma unroll
        for (int ks = 0; ks < 2; ks++) {
            const uint32_t ko = (uint32_t)(ks * 32);
            uint32_t aH[4][4];
            #pragma unroll
            for (int mt = 0; mt < 4; mt++)
                ldsm4(aH[mt], st + aoff + (uint32_t)(mt * 16 * APITCH) + ko);
            uint32_t bH[2][4];
            #pragma unroll
            for (int nh = 0; nh < 2; nh++)
                ldsm4(bH[nh], st + 2 * PLANE + boff + (uint32_t)(nh * 16 * APITCH) + ko);
            #pragma unroll
            for (int mt = 0; mt < 4; mt++)
                #pragma unroll
                for (int nt = 0; nt < 4; nt++)
                    mma16(acc[mt][nt], aH[mt][0], aH[mt][1], aH[mt][2], aH[mt][3],
                          bH[nt >> 1][(nt & 1) * 2], bH[nt >> 1][(nt & 1) * 2 + 1]);
            {
                uint32_t bL[2][4];
                #pragma unroll
                for (int nh = 0; nh < 2; nh++)
                    ldsm4(bL[nh], st + 3 * PLANE + boff + (uint32_t)(nh * 16 * APITCH) + ko);
                #pragma unroll
                for (int mt = 0; mt < 4; mt++)
                    #pragma unroll
                    for (int nt = 0; nt < 4; nt++)
                        mma16(acc[mt][nt], aH[mt][0], aH[mt][1], aH[mt][2], aH[mt][3],
                              bL[nt >> 1][(nt & 1) * 2], bL[nt >> 1][(nt & 1) * 2 + 1]);
            }
            {
                uint32_t aL[4][4];
                #pragma unroll
                for (int mt = 0; mt < 4; mt++)
                    ldsm4(aL[mt], st + PLANE + aoff + (uint32_t)(mt * 16 * APITCH) + ko);
                #pragma unroll
                for (int mt = 0; mt < 4; mt++)
                    #pragma unroll
                    for (int nt = 0; nt < 4; nt++)
                        mma16(acc[mt][nt], aL[mt][0], aL[mt][1], aL[mt][2], aL[mt][3],
                              bH[nt >> 1][(nt & 1) * 2], bH[nt >> 1][(nt & 1) * 2 + 1]);
            }
        }
    }

    const int b    = l0 >> 13;
    const int lloc = l0 & (SEQ - 1);
    #pragma unroll
    for (int mt = 0; mt < 4; mt++) {
        const int lbase = lloc + m0 + mt * 16 + g;
        #pragma unroll
        for (int nt = 0; nt < 4; nt++) {
            const int d0 = n0 + nw0 + nt * 8 + 2 * tig;
            float4 cc = acc[mt][nt];
            float* pa = g_XT + (((size_t)(b * DIM + d0)) << 13) + lbase;
            float* pb = g_XT + (((size_t)(b * DIM + d0 + 1)) << 13) + lbase;
            pa[0] = cc.x; pb[0] = cc.y;
            pa[8] = cc.z; pb[8] = cc.w;
        }
    }
}

// ---------------------------------------------------------------------------
// Kernel 4: per-(b,d) FFT convolution, in place on g_XT rows (R13-best form:
// two-buffer, 512 threads). Fused ends: fwd stage 1 reads global directly,
// inverse stage 1 applies the spectral multiply, inverse final stage writes
// only the needed half straight to global.
// ---------------------------------------------------------------------------
__global__ void __launch_bounds__(512, 1)
conv_kernel() {
    extern __shared__ float2 fb[];
    float2* A  = fb;
    float2* Bu = fb + FFT_BUF;

    const int tid = threadIdx.x;
    const int d   = blockIdx.x >> 2;
    const int b   = blockIdx.x & 3;

    float2* row = (float2*)(g_XT + (((size_t)(b * DIM + d)) << 13));
    const float2* vs = g_VS + ((size_t)d << 13);

    // ---- forward FFT: stage 1 (Ns=1, no twiddle) straight from global ----
    #pragma unroll
    for (int it = 0; it < 2; it++) {
        int j = tid + it * 512;
        float2 v[8];
        #pragma unroll
        for (int r = 0; r < 8; r++)
            v[r] = (r < 4) ? row[j + r * 1024] : make_float2(0.0f, 0.0f);
        dft8<-1>(v);
        #pragma unroll
        for (int r = 0; r < 8; r++) A[SMX(j * 8 + r)] = v[r];
    }
    __syncthreads();
    fft_stage<-1>(A, Bu, 8, tid);
    fft_stage<-1>(Bu, A, 64, tid);
    fft_stage<-1>(A, Bu, 512, tid);
    fft_r2<-1>(Bu, A, tid);            // spectrum now in A

    // ---- inverse FFT: stage 1 (Ns=1) with fused spectral multiply ----
    #pragma unroll
    for (int it = 0; it < 2; it++) {
        int j = tid + it * 512;
        float2 v[8];
        #pragma unroll
        for (int r = 0; r < 8; r++) {
            int idx = j + r * 1024;
            v[r] = cmul(A[SMX(idx)], vs[idx]);
        }
        dft8<1>(v);
        #pragma unroll
        for (int r = 0; r < 8; r++) Bu[SMX(j * 8 + r)] = v[r];
    }
    __syncthreads();
    fft_stage<1>(Bu, A, 8, tid);
    fft_stage<1>(A, Bu, 64, tid);
    fft_stage<1>(Bu, A, 512, tid);

    // ---- inverse final radix-2: write the needed half straight to global ----
    const float angc2 = 6.283185307179586f / 8192.0f;
    #pragma unroll
    for (int it = 0; it < 8; it++) {
        int j = tid + it * 512;            // 0..4095
        float c, sn;
        __sincosf(angc2 * (float)j, &sn, &c);
        float2 v0 = A[SMX(j)];
        float2 v1 = cmul(A[SMX(j + 4096)], make_float2(c, sn));
        row[j] = make_float2(v0.x + v1.x, v0.y + v1.y);
    }
}

// ---------------------------------------------------------------------------
// Kernel 5: transpose g_XT (B,D,L) -> out (B,L,D)
// ---------------------------------------------------------------------------
__global__ void __launch_bounds__(256, 4)
transpose_kernel(float* __restrict__ out) {
    __shared__ float t[32][33];
    const int b  = blockIdx.z;
    const int l0 = blockIdx.x * 32;
    const int d0 = blockIdx.y * 32;
    const int tx = threadIdx.x, ty = threadIdx.y;   // 32 x 8

    const float* src = g_XT + (size_t)b * DIM * SEQ;
    #pragma unroll
    for (int i = 0; i < 4; i++)
        t[ty + i * 8][tx] = src[(size_t)(d0 + ty + i * 8) * SEQ + l0 + tx];
    __syncthreads();
    float* dst = out + (size_t)b * SEQ * DIM;
    #pragma unroll
    for (int i = 0; i < 4; i++)
        dst[(size_t)(l0 + ty + i * 8) * DIM + d0 + tx] = t[tx][ty + i * 8];
}

// ---------------------------------------------------------------------------
// launch: prep(1), vs(2), gemm(3), conv(4), transpose(5)
// ---------------------------------------------------------------------------
extern "C" void kernel_launch(void* const* d_in, const int* in_sizes, int n_in,
                              void* d_out, int out_size) {
    const float* x   = (const float*)d_in[0];
    const float* phi = (const float*)d_in[1];
    const float* Mi  = (const float*)d_in[2];
    const float* Mf  = (const float*)d_in[3];
    float* out = (float*)d_out;

    cudaFuncSetAttribute(prep_kernel, cudaFuncAttributeMaxDynamicSharedMemorySize, FFT_SMEM_BYTES);
    cudaFuncSetAttribute(conv_kernel, cudaFuncAttributeMaxDynamicSharedMemorySize, FFT_SMEM_BYTES);
    cudaFuncSetAttribute(gemm_kernel, cudaFuncAttributeMaxDynamicSharedMemorySize, GEMM_DYN_BYTES);

    prep_kernel<<<PREP_GRID, 512, FFT_SMEM_BYTES>>>(x, phi, Mi);
    vs_kernel<<<768, 256>>>(Mf);
    gemm_kernel<<<dim3(DIM / 128, (BATCH * SEQ) / 128), 256, GEMM_DYN_BYTES>>>(0);
    conv_kernel<<<BATCH * DIM, 512, FFT_SMEM_BYTES>>>();
    transpose_kernel<<<dim3(SEQ / 32, DIM / 32, BATCH), dim3(32, 8)>>>(out);
}